// round 12
// baseline (speedup 1.0000x reference)
#include <cuda_runtime.h>
#include <math.h>

#define NS 256       // sequence length S
#define NB 64        // batch B
#define NE 300       // embedding dim E
#define NH2 256      // hidden per direction
#define NG 1024      // 4*NH2 gates
#define NM 16384     // S*B flattened rows
#define NT 10        // tags
#define IDX_START 8
#define IDX_STOP 9

// LSTM cluster geometry
#define CLS 8        // CTAs per cluster
#define LANES 8      // batch lanes per cluster
#define UPC 32       // hidden units per CTA (NH2 / CLS)
#define ROWS 128     // gate rows per CTA (4 * UPC)

#define HPITCH 264                    // padded h row (per lane)
#define HBUF (LANES * HPITCH)         // 2112 floats per buffer
#define ELP 132                       // red: el pitch (132 fl = 528 B, 16B-mult)
#define REDK (LANES * ELP)            // 1056 floats per k-slice
#define WPITCH 34                     // padded k pitch (8B-aligned, bank rg*2)
#define WBLK (16 * WPITCH)            // 544 floats per (ks,half,j) block

// dynamic smem layout (floats)
#define SW_OFF 0                          // 64 * 544 = 34816 floats
#define HB_OFF 34816                      // 2 * 2112
#define RED_OFF (HB_OFF + 2 * HBUF)       // 39040, 8 * 1056
#define DSM_FLOATS (RED_OFF + 8 * REDK)   // 47488 floats = 189952 B

#define LOG2E 1.4426950408889634f

// ------------------- scratch (static device allocations) -------------------
// G2 layout: [dir][s][cb][rank][gate*32+eu][el]  (contiguous 4KB per CTA-step)
__device__ __align__(256) float g_G2[2][NS][8][8][4 * UPC * LANES];  // 134 MB
__device__ __align__(256) float g_lstm[NM][2 * NH2];                 // 33.5 MB
__device__ __align__(256) float g_feats[NM][NT];                     // 0.66 MB

// ------------------- fast-math helpers (MUFU, ~1e-6 accuracy) --------------
__device__ __forceinline__ float ex2f(float x) {
    float r; asm("ex2.approx.ftz.f32 %0, %1;" : "=f"(r) : "f"(x)); return r;
}
__device__ __forceinline__ float rcpf(float x) {
    float r; asm("rcp.approx.ftz.f32 %0, %1;" : "=f"(r) : "f"(x)); return r;
}
__device__ __forceinline__ float sigf(float x) {
    // 1/(1+e^-x); x->-inf: ex2(+big)=inf -> rcp(inf)=0 (correct)
    return rcpf(1.0f + ex2f(-x * LOG2E));
}
__device__ __forceinline__ float tanhf_fast(float x) {
    // (e^{2x}-1)/(e^{2x}+1); clamp exponent high side; FTZ handles low side (-1)
    const float t = fminf(x * (2.0f * LOG2E), 126.0f);
    const float e = ex2f(t);
    return (e - 1.0f) * rcpf(e + 1.0f);
}

__device__ __forceinline__ unsigned smem_u32(const void* p) {
    unsigned a;
    asm("{ .reg .u64 t; cvta.to.shared.u64 t, %1; cvt.u32.u64 %0, t; }" : "=r"(a) : "l"(p));
    return a;
}
__device__ __forceinline__ unsigned ctarank() {
    unsigned r; asm("mov.u32 %0, %%cluster_ctarank;" : "=r"(r)); return r;
}
__device__ __forceinline__ void ffma2(unsigned long long& d,
                                      unsigned long long a, unsigned long long b) {
    asm("fma.rn.f32x2 %0, %1, %2, %0;" : "+l"(d) : "l"(a), "l"(b));
}
__device__ __forceinline__ float hadd2(unsigned long long v) {
    float lo, hi;
    asm("mov.b64 {%0, %1}, %2;" : "=f"(lo), "=f"(hi) : "l"(v));
    return lo + hi;
}
__device__ __forceinline__ unsigned long long pk2(float x) {
    unsigned long long d;
    asm("mov.b64 %0, {%1, %1};" : "=l"(d) : "f"(x));
    return d;
}
__device__ __forceinline__ void upk2(unsigned long long v, float& lo, float& hi) {
    asm("mov.b64 {%0, %1}, %2;" : "=f"(lo), "=f"(hi) : "l"(v));
}

// ------------------- input projection GEMM (f32x2 packed) ------------------
// C[t][col] = sum_e emb[tok[t]][e] * wih[col][e] + (bih+bhh)[col]
// A-values stored PRE-DUPLICATED in smem ((x,x) pairs) so the inner loop is
// pure LDS.128 + FFMA2 -- no per-element pack movs.
__global__ __launch_bounds__(256) void k_input_gemm(
    const int* __restrict__ tok, const float* __restrict__ emb,
    const float* __restrict__ wih, const float* __restrict__ bih,
    const float* __restrict__ bhh, int dir) {
    __shared__ float As2[8][256];   // dup pairs: As2[kk][2i]=As2[kk][2i+1]=A
    __shared__ float Bs[8][128];
    __shared__ int stok[128];

    const int t0 = blockIdx.x * 128;
    const int j0 = blockIdx.y * 128;
    const int tid = threadIdx.x;
    if (tid < 128) stok[tid] = tok[t0 + tid];
    __syncthreads();

    const int tx = tid & 15;
    const int ty = tid >> 4;
    const int r = tid >> 1;
    const int q = tid & 1;

    unsigned long long acc[8][4];   // [row i][col-pair jp]
    #pragma unroll
    for (int i = 0; i < 8; ++i)
        #pragma unroll
        for (int jp = 0; jp < 4; ++jp) acc[i][jp] = 0ull;

    for (int k0 = 0; k0 < NE; k0 += 8) {
        const int kc = k0 + q * 4;
        float4 av = make_float4(0.f, 0.f, 0.f, 0.f);
        float4 bv = make_float4(0.f, 0.f, 0.f, 0.f);
        if (kc < NE) {  // NE % 4 == 0 so a guarded float4 never straddles the edge
            av = *(const float4*)(emb + (size_t)stok[r] * NE + kc);
            bv = *(const float4*)(wih + (size_t)(j0 + r) * NE + kc);
        }
        __syncthreads();  // previous tile fully consumed
        *(unsigned long long*)&As2[q * 4 + 0][2 * r] = pk2(av.x);
        *(unsigned long long*)&As2[q * 4 + 1][2 * r] = pk2(av.y);
        *(unsigned long long*)&As2[q * 4 + 2][2 * r] = pk2(av.z);
        *(unsigned long long*)&As2[q * 4 + 3][2 * r] = pk2(av.w);
        Bs[q * 4 + 0][r] = bv.x; Bs[q * 4 + 1][r] = bv.y;
        Bs[q * 4 + 2][r] = bv.z; Bs[q * 4 + 3][r] = bv.w;
        __syncthreads();
        #pragma unroll
        for (int kk = 0; kk < 8; ++kk) {
            ulonglong2 a01 = *(const ulonglong2*)&As2[kk][ty * 16];
            ulonglong2 a23 = *(const ulonglong2*)&As2[kk][ty * 16 + 4];
            ulonglong2 a45 = *(const ulonglong2*)&As2[kk][ty * 16 + 8];
            ulonglong2 a67 = *(const ulonglong2*)&As2[kk][ty * 16 + 12];
            ulonglong2 b01 = *(const ulonglong2*)&Bs[kk][tx * 8];      // pairs 0,1
            ulonglong2 b23 = *(const ulonglong2*)&Bs[kk][tx * 8 + 4];  // pairs 2,3
            const unsigned long long ad[8] = {a01.x, a01.y, a23.x, a23.y,
                                              a45.x, a45.y, a67.x, a67.y};
            #pragma unroll
            for (int i = 0; i < 8; ++i) {
                ffma2(acc[i][0], ad[i], b01.x);
                ffma2(acc[i][1], ad[i], b01.y);
                ffma2(acc[i][2], ad[i], b23.x);
                ffma2(acc[i][3], ad[i], b23.y);
            }
        }
    }

    // unpack pairs -> accf[i][j]
    float accf[8][8];
    #pragma unroll
    for (int i = 0; i < 8; ++i)
        #pragma unroll
        for (int jp = 0; jp < 4; ++jp)
            upk2(acc[i][jp], accf[i][2 * jp], accf[i][2 * jp + 1]);

    // epilogue: thread covers t = t0+ty*8+i (i=0..7 -> el), col = j0+tx*8+j (-> eu)
    const int jj = j0 + tx * 8;
    float bsum[8];
    #pragma unroll
    for (int j = 0; j < 8; ++j) bsum[j] = bih[jj + j] + bhh[jj + j];

    const int tb = t0 + ty * 8;          // aligned to 8 -> el = i
    const int s = tb >> 6;
    const int cb = (tb >> 3) & 7;
    const int gate = jj >> 8;
    const int rank = (jj >> 5) & 7;
    const int eu0 = jj & 31;             // in {0,8,16,24}; j<8 stays in-range
    float* base2 = &g_G2[dir][s][cb][rank][0] + gate * 256 + eu0 * 8;

    #pragma unroll
    for (int j = 0; j < 8; ++j) {
        float4 lo = make_float4(accf[0][j] + bsum[j], accf[1][j] + bsum[j],
                                accf[2][j] + bsum[j], accf[3][j] + bsum[j]);
        float4 hi = make_float4(accf[4][j] + bsum[j], accf[5][j] + bsum[j],
                                accf[6][j] + bsum[j], accf[7][j] + bsum[j]);
        *(float4*)(base2 + j * 8) = lo;
        *(float4*)(base2 + j * 8 + 4) = hi;
    }
}

// ------------------- clustered recurrent LSTM ------------------------------
// 128 CTAs = 16 clusters of 8, 512 threads (16 warps, 4/SMSP).
// Matvec: warp=(ks,half), thread=(lg,rg) -> 4 rows x 4 lanes x 32 k, f32x2 FMA.
// Phase D uses MUFU-based sigmoid/tanh (ex2/rcp approx, ~1e-6) instead of the
// slow software expf/tanhf -- phase D sits on the per-step critical path.
__global__ __launch_bounds__(512, 1) __cluster_dims__(CLS, 1, 1)
void k_lstm(const float* __restrict__ whh_f, const float* __restrict__ whh_b,
            const float* __restrict__ h0, const float* __restrict__ c0) {
    extern __shared__ float dsm[];
    const int tid = threadIdx.x;
    const unsigned rank = ctarank();
    const int cid = blockIdx.x >> 3;
    const int dir = cid >> 3;
    const int cb = cid & 7;
    const int bg0 = cb * LANES;
    const int u0 = rank * UPC;

    const float* __restrict__ whh = dir ? whh_b : whh_f;

    // ---- stage weight slice: W2[(ks*2+half)*4 + j][rg][kk(pitch 34)]
    for (int idx = tid; idx < ROWS * NH2; idx += 512) {
        const int row = idx >> 8;          // local gate row 0..127
        const int k = idx & 255;
        const int half = row >> 6, rp = row & 63;
        const int rg = rp >> 2, j = rp & 3;
        const int ks = k >> 5, kk = k & 31;
        const int grow = ((row >> 5) << 8) + u0 + (row & 31);
        dsm[SW_OFF + ((ks * 2 + half) * 4 + j) * WBLK + rg * WPITCH + kk] =
            whh[(size_t)grow * NH2 + k];
    }
    // ---- init h buffer 0: hT[el][k]
    for (int jdx = tid; jdx < LANES * NH2; jdx += 512) {
        const int l = jdx >> 8, k = jdx & 255;
        dsm[HB_OFF + l * HPITCH + k] = h0[(size_t)(dir * NB + bg0 + l) * NH2 + k];
    }
    // ---- phase-2 role (tid<256): (unit eu, lane el)
    const int eu = tid >> 3, el = tid & 7;
    float c = 0.0f;
    if (tid < 256)
        c = c0[(size_t)(dir * NB + bg0 + el) * NH2 + u0 + eu];

    // ---- peer hbuf base addresses
    const unsigned hb_local = smem_u32(&dsm[HB_OFF]);
    unsigned hb_peer[CLS];
    #pragma unroll
    for (int j = 0; j < CLS; ++j)
        asm("mapa.shared::cluster.u32 %0, %1, %2;"
            : "=r"(hb_peer[j]) : "r"(hb_local), "r"(j));

    // ---- matvec role
    const int w = tid >> 5;
    const int ks = w >> 1;
    const int half = w & 1;
    const int lane = tid & 31;
    const int lg = lane >> 4;       // 0..1 (4-lane group)
    const int rg = lane & 15;       // 0..15 (4-row group)
    const int wb0 = SW_OFF + (ks * 2 + half) * 4 * WBLK + rg * WPITCH;
    const int hbase = HB_OFF + lg * 4 * HPITCH + ks * 32;
    // phase-C store base: red[ks][el = lg*4 + li][row = half*64 + rg*4 .. +3]
    const int cbase = RED_OFF + ks * REDK + lg * 4 * ELP + half * 64 + rg * 4;

    // CTA-step base into g_G2
    const float* __restrict__ G2 = &g_G2[dir][0][cb][rank][0];

    __syncthreads();
    asm volatile("barrier.cluster.arrive.aligned;" ::: "memory");
    asm volatile("barrier.cluster.wait.aligned;" ::: "memory");

    int p = 0;
    for (int si = 0; si < NS; ++si) {
        const int s = dir ? (NS - 1 - si) : si;

        // phase A (tid<256): coalesced input-gate loads
        float gin0 = 0.f, gin1 = 0.f, gin2 = 0.f, gin3 = 0.f;
        if (tid < 256) {
            const float* Gp = G2 + (size_t)s * (8 * 8 * 1024) + tid;
            gin0 = Gp[0];
            gin1 = Gp[256];
            gin2 = Gp[512];
            gin3 = Gp[768];
        }

        // phase B: matvec, 4 rows (j) x 4 lanes (li) x 32 k
        unsigned long long accp[16];
        #pragma unroll
        for (int i = 0; i < 16; ++i) accp[i] = 0ull;

        const float* Hb = &dsm[hbase + p * HBUF];
        #pragma unroll
        for (int kq = 0; kq < 8; ++kq) {
            ulonglong2 hq[4];
            #pragma unroll
            for (int li = 0; li < 4; ++li)
                hq[li] = *(const ulonglong2*)(Hb + li * HPITCH + kq * 4);
            #pragma unroll
            for (int j = 0; j < 4; ++j) {
                const unsigned long long wlo =
                    *(const unsigned long long*)&dsm[wb0 + j * WBLK + kq * 4];
                const unsigned long long whi =
                    *(const unsigned long long*)&dsm[wb0 + j * WBLK + kq * 4 + 2];
                #pragma unroll
                for (int li = 0; li < 4; ++li) {
                    ffma2(accp[j * 4 + li], wlo, hq[li].x);
                    ffma2(accp[j * 4 + li], whi, hq[li].y);
                }
            }
        }

        // phase C: stage partials  red[ks][el][row], one float4 (4 rows) per el
        #pragma unroll
        for (int li = 0; li < 4; ++li) {
            float4 v = make_float4(hadd2(accp[0 * 4 + li]), hadd2(accp[1 * 4 + li]),
                                   hadd2(accp[2 * 4 + li]), hadd2(accp[3 * 4 + li]));
            *(float4*)&dsm[cbase + li * ELP] = v;  // 16B-aligned (ELP=132)
        }
        __syncthreads();

        // phase D (tid<256): reduce 8 k-slices + LSTM cell + h broadcast
        if (tid < 256) {
            float g0 = gin0, g1 = gin1, g2 = gin2, g3 = gin3;
            const float* rb = &dsm[RED_OFF + el * ELP];
            #pragma unroll
            for (int kk = 0; kk < 8; ++kk) {
                const float* rk = rb + kk * REDK;
                g0 += rk[eu];
                g1 += rk[32 + eu];
                g2 += rk[64 + eu];
                g3 += rk[96 + eu];
            }
            const float iv = sigf(g0), fv = sigf(g1);
            const float gv = tanhf_fast(g2), ov = sigf(g3);
            c = fv * c + iv * gv;
            const float h = ov * tanhf_fast(c);

            const unsigned off = (((p ^ 1) * HBUF) + el * HPITCH + u0 + eu) * 4u;
            #pragma unroll
            for (int j = 0; j < CLS; ++j)
                asm volatile("st.shared::cluster.f32 [%0], %1;"
                             :: "r"(hb_peer[j] + off), "f"(h) : "memory");
        }
        __syncthreads();   // own h-stores visible locally for phase E

        // phase E (tid<256): coalesced g_lstm writeback from local buffer p^1
        if (tid < 256) {
            const int el2 = tid >> 5, ul = tid & 31;
            const float hv = dsm[HB_OFF + (p ^ 1) * HBUF + el2 * HPITCH + u0 + ul];
            g_lstm[s * NB + bg0 + el2][dir * NH2 + u0 + ul] = hv;
        }

        // phase F: cluster barrier (release peer stores / acquire for next read)
        asm volatile("barrier.cluster.arrive.aligned;" ::: "memory");
        asm volatile("barrier.cluster.wait.aligned;" ::: "memory");
        p ^= 1;
    }
}

// ------------------- emission features: lstm_out @ W_out^T + b_out ---------
__global__ __launch_bounds__(256) void k_feats(const float* __restrict__ Wout,
                                               const float* __restrict__ bout) {
    __shared__ float sW[NT][2 * NH2];
    const int tid = threadIdx.x;
    for (int i = tid; i < NT * 2 * NH2; i += 256) sW[i / (2 * NH2)][i % (2 * NH2)] = Wout[i];
    __syncthreads();

    const int warp = tid >> 5, lane = tid & 31;
    const int n = blockIdx.x * 8 + warp;
    const float4* row = (const float4*)&g_lstm[n][0];

    float pAcc[NT];
    #pragma unroll
    for (int t = 0; t < NT; ++t) pAcc[t] = 0.0f;
    for (int q = lane; q < 128; q += 32) {
        const float4 v = row[q];
        #pragma unroll
        for (int t = 0; t < NT; ++t) {
            const float4 wv = ((const float4*)&sW[t][0])[q];
            pAcc[t] += v.x * wv.x + v.y * wv.y + v.z * wv.z + v.w * wv.w;
        }
    }
    #pragma unroll
    for (int off = 16; off; off >>= 1)
        #pragma unroll
        for (int t = 0; t < NT; ++t)
            pAcc[t] += __shfl_down_sync(0xffffffffu, pAcc[t], off);
    if (lane == 0) {
        #pragma unroll
        for (int t = 0; t < NT; ++t) g_feats[n][t] = pAcc[t] + bout[t];
    }
}

// ------------------- Viterbi decode (1 warp per batch element) -------------
__global__ void k_viterbi(const float* __restrict__ trans, float* __restrict__ out) {
    const int b = blockIdx.x;
    const int lane = threadIdx.x;
    __shared__ float st[NT * NT];
    __shared__ unsigned char bp[NS][NT];
    for (int i = lane; i < NT * NT; i += 32) st[i] = trans[i];
    __syncwarp();

    float fv = (lane == IDX_START) ? 0.0f : -10000.0f;
    for (int s = 0; s < NS; ++s) {
        float best = -3.4e38f;
        int barg = 0;
        const float cur = fv;
        #pragma unroll
        for (int p = 0; p < NT; ++p) {
            const float fp = __shfl_sync(0xffffffffu, cur, p);
            if (lane < NT) {
                const float v = fp + st[lane * NT + p];
                if (v > best) { best = v; barg = p; }
            }
        }
        float feat = 0.0f;
        if (lane < NT) feat = g_feats[b * NS + s][lane];
        fv = best + feat;
        if (lane < NT) bp[s][lane] = (unsigned char)barg;
        __syncwarp();
    }
    float m = (lane < NT) ? (fv + st[IDX_STOP * NT + lane]) : -3.4e38f;
    int mi = lane;
    #pragma unroll
    for (int off = 16; off; off >>= 1) {
        const float om = __shfl_down_sync(0xffffffffu, m, off);
        const int oi = __shfl_down_sync(0xffffffffu, mi, off);
        if (om > m || (om == m && oi < mi)) { m = om; mi = oi; }
    }
    if (lane == 0) {
        out[b] = m;
        int best = mi;
        for (int s = NS - 1; s >= 0; --s) {
            out[NB + b * NS + s] = (float)best;
            best = bp[s][best];
        }
    }
}

// ------------------- launcher ----------------------------------------------
extern "C" void kernel_launch(void* const* d_in, const int* in_sizes, int n_in,
                              void* d_out, int out_size) {
    const int*   sent  = (const int*)d_in[0];
    const float* emb   = (const float*)d_in[1];
    const float* wih_f = (const float*)d_in[2];
    const float* whh_f = (const float*)d_in[3];
    const float* bih_f = (const float*)d_in[4];
    const float* bhh_f = (const float*)d_in[5];
    const float* wih_b = (const float*)d_in[6];
    const float* whh_b = (const float*)d_in[7];
    const float* bih_b = (const float*)d_in[8];
    const float* bhh_b = (const float*)d_in[9];
    const float* Wout  = (const float*)d_in[10];
    const float* bout  = (const float*)d_in[11];

    const float *trans, *h0, *c0;
    if (n_in > 12 && in_sizes[12] == NT * NT) {
        trans = (const float*)d_in[12];
        h0    = (const float*)d_in[13];
        c0    = (const float*)d_in[14];
    } else {
        h0    = (const float*)d_in[12];
        c0    = (const float*)d_in[13];
        trans = (const float*)d_in[14];
    }

    static int smem_set = 0;
    const int lstm_smem = DSM_FLOATS * (int)sizeof(float);  // ~185.5 KB
    if (!smem_set) {
        cudaFuncSetAttribute(k_lstm, cudaFuncAttributeMaxDynamicSharedMemorySize,
                             lstm_smem);
        smem_set = 1;
    }

    {
        dim3 gg(NM / 128, NG / 128);
        k_input_gemm<<<gg, 256>>>(sent, emb, wih_f, bih_f, bhh_f, 0);
        k_input_gemm<<<gg, 256>>>(sent, emb, wih_b, bih_b, bhh_b, 1);
    }
    k_lstm<<<128, 512, lstm_smem>>>(whh_f, whh_b, h0, c0);
    k_feats<<<NM / 8, 256>>>(Wout, bout);
    k_viterbi<<<NB, 32>>>(trans, (float*)d_out);
}

// round 17
// speedup vs baseline: 1.6285x; 1.6285x over previous
#include <cuda_runtime.h>
#include <math.h>

#define NS 256       // sequence length S
#define NB 64        // batch B
#define NE 300       // embedding dim E
#define NH2 256      // hidden per direction
#define NG 1024      // 4*NH2 gates
#define NM 16384     // S*B flattened rows
#define NT 10        // tags
#define IDX_START 8
#define IDX_STOP 9

// LSTM cluster geometry
#define CLS 8        // CTAs per cluster
#define LANES 8      // batch lanes per cluster
#define UPC 32       // hidden units per CTA (NH2 / CLS)
#define ROWS 128     // gate rows per CTA (4 * UPC)

#define HPITCH 264                    // padded h row (per lane)
#define HBUF (LANES * HPITCH)         // 2112 floats per buffer
#define ELP 132                       // red: el pitch (132 fl = 528 B, 16B-mult)
#define REDK (LANES * ELP)            // 1056 floats per k-slice
#define WPITCH 34                     // padded k pitch (8B-aligned, bank rg*2)
#define WBLK (16 * WPITCH)            // 544 floats per (ks,half,j) block

// dynamic smem layout (floats)
#define SW_OFF 0                          // 64 * 544 = 34816 floats
#define HB_OFF 34816                      // 2 * 2112
#define RED_OFF (HB_OFF + 2 * HBUF)       // 39040, 8 * 1056
#define DSM_FLOATS (RED_OFF + 8 * REDK)   // 47488 floats = 189952 B

#define LOG2E 1.4426950408889634f

// ------------------- scratch (static device allocations) -------------------
// G2 layout: [dir][s][cb][rank][gate*32+eu][el]  (contiguous 4KB per CTA-step)
__device__ __align__(256) float g_G2[2][NS][8][8][4 * UPC * LANES];  // 134 MB
__device__ __align__(256) float g_lstm[NM][2 * NH2];                 // 33.5 MB
__device__ __align__(256) float g_feats[NM][NT];                     // 0.66 MB

// ------------------- fast-math helpers (MUFU, ~1e-6 accuracy) --------------
__device__ __forceinline__ float ex2f(float x) {
    float r; asm("ex2.approx.ftz.f32 %0, %1;" : "=f"(r) : "f"(x)); return r;
}
__device__ __forceinline__ float rcpf(float x) {
    float r; asm("rcp.approx.ftz.f32 %0, %1;" : "=f"(r) : "f"(x)); return r;
}
__device__ __forceinline__ float sigf(float x) {
    // 1/(1+e^-x); x->-inf: ex2(+big)=inf -> rcp(inf)=0 (correct)
    return rcpf(1.0f + ex2f(-x * LOG2E));
}
__device__ __forceinline__ float tanhf_fast(float x) {
    // (e^{2x}-1)/(e^{2x}+1); clamp exponent high side; FTZ handles low side (-1)
    const float t = fminf(x * (2.0f * LOG2E), 126.0f);
    const float e = ex2f(t);
    return (e - 1.0f) * rcpf(e + 1.0f);
}

__device__ __forceinline__ unsigned smem_u32(const void* p) {
    unsigned a;
    asm("{ .reg .u64 t; cvta.to.shared.u64 t, %1; cvt.u32.u64 %0, t; }" : "=r"(a) : "l"(p));
    return a;
}
__device__ __forceinline__ unsigned ctarank() {
    unsigned r; asm("mov.u32 %0, %%cluster_ctarank;" : "=r"(r)); return r;
}
__device__ __forceinline__ void ffma2(unsigned long long& d,
                                      unsigned long long a, unsigned long long b) {
    asm("fma.rn.f32x2 %0, %1, %2, %0;" : "+l"(d) : "l"(a), "l"(b));
}
__device__ __forceinline__ float hadd2(unsigned long long v) {
    float lo, hi;
    asm("mov.b64 {%0, %1}, %2;" : "=f"(lo), "=f"(hi) : "l"(v));
    return lo + hi;
}
__device__ __forceinline__ unsigned long long pk2(float x) {
    unsigned long long d;
    asm("mov.b64 %0, {%1, %1};" : "=l"(d) : "f"(x));
    return d;
}
__device__ __forceinline__ void upk2(unsigned long long v, float& lo, float& hi) {
    asm("mov.b64 {%0, %1}, %2;" : "=f"(lo), "=f"(hi) : "l"(v));
}

// ------------------- input projection GEMM (f32x2 packed) ------------------
// EXACT R11 version (proven 2256us config) -- pk2 in inner loop, As 128-wide.
__global__ __launch_bounds__(256) void k_input_gemm(
    const int* __restrict__ tok, const float* __restrict__ emb,
    const float* __restrict__ wih, const float* __restrict__ bih,
    const float* __restrict__ bhh, int dir) {
    __shared__ float As[8][128];
    __shared__ float Bs[8][128];
    __shared__ int stok[128];

    const int t0 = blockIdx.x * 128;
    const int j0 = blockIdx.y * 128;
    const int tid = threadIdx.x;
    if (tid < 128) stok[tid] = tok[t0 + tid];
    __syncthreads();

    const int tx = tid & 15;
    const int ty = tid >> 4;
    const int r = tid >> 1;
    const int q = tid & 1;

    unsigned long long acc[8][4];   // [row i][col-pair jp]
    #pragma unroll
    for (int i = 0; i < 8; ++i)
        #pragma unroll
        for (int jp = 0; jp < 4; ++jp) acc[i][jp] = 0ull;

    for (int k0 = 0; k0 < NE; k0 += 8) {
        const int kc = k0 + q * 4;
        float4 av = make_float4(0.f, 0.f, 0.f, 0.f);
        float4 bv = make_float4(0.f, 0.f, 0.f, 0.f);
        if (kc < NE) {  // NE % 4 == 0 so a guarded float4 never straddles the edge
            av = *(const float4*)(emb + (size_t)stok[r] * NE + kc);
            bv = *(const float4*)(wih + (size_t)(j0 + r) * NE + kc);
        }
        __syncthreads();  // previous tile fully consumed
        As[q * 4 + 0][r] = av.x; As[q * 4 + 1][r] = av.y;
        As[q * 4 + 2][r] = av.z; As[q * 4 + 3][r] = av.w;
        Bs[q * 4 + 0][r] = bv.x; Bs[q * 4 + 1][r] = bv.y;
        Bs[q * 4 + 2][r] = bv.z; Bs[q * 4 + 3][r] = bv.w;
        __syncthreads();
        #pragma unroll
        for (int kk = 0; kk < 8; ++kk) {
            float a[8];
            *(float4*)&a[0] = *(const float4*)&As[kk][ty * 8];
            *(float4*)&a[4] = *(const float4*)&As[kk][ty * 8 + 4];
            ulonglong2 b01 = *(const ulonglong2*)&Bs[kk][tx * 8];      // pairs 0,1
            ulonglong2 b23 = *(const ulonglong2*)&Bs[kk][tx * 8 + 4];  // pairs 2,3
            #pragma unroll
            for (int i = 0; i < 8; ++i) {
                const unsigned long long ap = pk2(a[i]);
                ffma2(acc[i][0], ap, b01.x);
                ffma2(acc[i][1], ap, b01.y);
                ffma2(acc[i][2], ap, b23.x);
                ffma2(acc[i][3], ap, b23.y);
            }
        }
    }

    // unpack pairs -> accf[i][j]
    float accf[8][8];
    #pragma unroll
    for (int i = 0; i < 8; ++i)
        #pragma unroll
        for (int jp = 0; jp < 4; ++jp)
            upk2(acc[i][jp], accf[i][2 * jp], accf[i][2 * jp + 1]);

    // epilogue: thread covers t = t0+ty*8+i (i=0..7 -> el), col = j0+tx*8+j (-> eu)
    const int jj = j0 + tx * 8;
    float bsum[8];
    #pragma unroll
    for (int j = 0; j < 8; ++j) bsum[j] = bih[jj + j] + bhh[jj + j];

    const int tb = t0 + ty * 8;          // aligned to 8 -> el = i
    const int s = tb >> 6;
    const int cb = (tb >> 3) & 7;
    const int gate = jj >> 8;
    const int rank = (jj >> 5) & 7;
    const int eu0 = jj & 31;             // in {0,8,16,24}; j<8 stays in-range
    float* base2 = &g_G2[dir][s][cb][rank][0] + gate * 256 + eu0 * 8;

    #pragma unroll
    for (int j = 0; j < 8; ++j) {
        float4 lo = make_float4(accf[0][j] + bsum[j], accf[1][j] + bsum[j],
                                accf[2][j] + bsum[j], accf[3][j] + bsum[j]);
        float4 hi = make_float4(accf[4][j] + bsum[j], accf[5][j] + bsum[j],
                                accf[6][j] + bsum[j], accf[7][j] + bsum[j]);
        *(float4*)(base2 + j * 8) = lo;
        *(float4*)(base2 + j * 8 + 4) = hi;
    }
}

// ------------------- clustered recurrent LSTM ------------------------------
// 128 CTAs = 16 clusters of 8, 512 threads (16 warps, 4/SMSP).
// Matvec: warp=(ks,half), thread=(lg,rg) -> 4 rows x 4 lanes x 32 k, f32x2 FMA.
// Phase D: MUFU-based sigmoid/tanh (ONLY change vs the proven R11 kernel).
__global__ __launch_bounds__(512, 1) __cluster_dims__(CLS, 1, 1)
void k_lstm(const float* __restrict__ whh_f, const float* __restrict__ whh_b,
            const float* __restrict__ h0, const float* __restrict__ c0) {
    extern __shared__ float dsm[];
    const int tid = threadIdx.x;
    const unsigned rank = ctarank();
    const int cid = blockIdx.x >> 3;
    const int dir = cid >> 3;
    const int cb = cid & 7;
    const int bg0 = cb * LANES;
    const int u0 = rank * UPC;

    const float* __restrict__ whh = dir ? whh_b : whh_f;

    // ---- stage weight slice: W2[(ks*2+half)*4 + j][rg][kk(pitch 34)]
    for (int idx = tid; idx < ROWS * NH2; idx += 512) {
        const int row = idx >> 8;          // local gate row 0..127
        const int k = idx & 255;
        const int half = row >> 6, rp = row & 63;
        const int rg = rp >> 2, j = rp & 3;
        const int ks = k >> 5, kk = k & 31;
        const int grow = ((row >> 5) << 8) + u0 + (row & 31);
        dsm[SW_OFF + ((ks * 2 + half) * 4 + j) * WBLK + rg * WPITCH + kk] =
            whh[(size_t)grow * NH2 + k];
    }
    // ---- init h buffer 0: hT[el][k]
    for (int jdx = tid; jdx < LANES * NH2; jdx += 512) {
        const int l = jdx >> 8, k = jdx & 255;
        dsm[HB_OFF + l * HPITCH + k] = h0[(size_t)(dir * NB + bg0 + l) * NH2 + k];
    }
    // ---- phase-2 role (tid<256): (unit eu, lane el)
    const int eu = tid >> 3, el = tid & 7;
    float c = 0.0f;
    if (tid < 256)
        c = c0[(size_t)(dir * NB + bg0 + el) * NH2 + u0 + eu];

    // ---- peer hbuf base addresses
    const unsigned hb_local = smem_u32(&dsm[HB_OFF]);
    unsigned hb_peer[CLS];
    #pragma unroll
    for (int j = 0; j < CLS; ++j)
        asm("mapa.shared::cluster.u32 %0, %1, %2;"
            : "=r"(hb_peer[j]) : "r"(hb_local), "r"(j));

    // ---- matvec role
    const int w = tid >> 5;
    const int ks = w >> 1;
    const int half = w & 1;
    const int lane = tid & 31;
    const int lg = lane >> 4;       // 0..1 (4-lane group)
    const int rg = lane & 15;       // 0..15 (4-row group)
    const int wb0 = SW_OFF + (ks * 2 + half) * 4 * WBLK + rg * WPITCH;
    const int hbase = HB_OFF + lg * 4 * HPITCH + ks * 32;
    // phase-C store base: red[ks][el = lg*4 + li][row = half*64 + rg*4 .. +3]
    const int cbase = RED_OFF + ks * REDK + lg * 4 * ELP + half * 64 + rg * 4;

    // CTA-step base into g_G2
    const float* __restrict__ G2 = &g_G2[dir][0][cb][rank][0];

    __syncthreads();
    asm volatile("barrier.cluster.arrive.aligned;" ::: "memory");
    asm volatile("barrier.cluster.wait.aligned;" ::: "memory");

    int p = 0;
    for (int si = 0; si < NS; ++si) {
        const int s = dir ? (NS - 1 - si) : si;

        // phase A (tid<256): coalesced input-gate loads
        float gin0 = 0.f, gin1 = 0.f, gin2 = 0.f, gin3 = 0.f;
        if (tid < 256) {
            const float* Gp = G2 + (size_t)s * (8 * 8 * 1024) + tid;
            gin0 = Gp[0];
            gin1 = Gp[256];
            gin2 = Gp[512];
            gin3 = Gp[768];
        }

        // phase B: matvec, 4 rows (j) x 4 lanes (li) x 32 k
        unsigned long long accp[16];
        #pragma unroll
        for (int i = 0; i < 16; ++i) accp[i] = 0ull;

        const float* Hb = &dsm[hbase + p * HBUF];
        #pragma unroll
        for (int kq = 0; kq < 8; ++kq) {
            ulonglong2 hq[4];
            #pragma unroll
            for (int li = 0; li < 4; ++li)
                hq[li] = *(const ulonglong2*)(Hb + li * HPITCH + kq * 4);
            #pragma unroll
            for (int j = 0; j < 4; ++j) {
                const unsigned long long wlo =
                    *(const unsigned long long*)&dsm[wb0 + j * WBLK + kq * 4];
                const unsigned long long whi =
                    *(const unsigned long long*)&dsm[wb0 + j * WBLK + kq * 4 + 2];
                #pragma unroll
                for (int li = 0; li < 4; ++li) {
                    ffma2(accp[j * 4 + li], wlo, hq[li].x);
                    ffma2(accp[j * 4 + li], whi, hq[li].y);
                }
            }
        }

        // phase C: stage partials  red[ks][el][row], one float4 (4 rows) per el
        #pragma unroll
        for (int li = 0; li < 4; ++li) {
            float4 v = make_float4(hadd2(accp[0 * 4 + li]), hadd2(accp[1 * 4 + li]),
                                   hadd2(accp[2 * 4 + li]), hadd2(accp[3 * 4 + li]));
            *(float4*)&dsm[cbase + li * ELP] = v;  // 16B-aligned (ELP=132)
        }
        __syncthreads();

        // phase D (tid<256): reduce 8 k-slices + LSTM cell + h broadcast
        if (tid < 256) {
            float g0 = gin0, g1 = gin1, g2 = gin2, g3 = gin3;
            const float* rb = &dsm[RED_OFF + el * ELP];
            #pragma unroll
            for (int kk = 0; kk < 8; ++kk) {
                const float* rk = rb + kk * REDK;
                g0 += rk[eu];
                g1 += rk[32 + eu];
                g2 += rk[64 + eu];
                g3 += rk[96 + eu];
            }
            const float iv = sigf(g0), fv = sigf(g1);
            const float gv = tanhf_fast(g2), ov = sigf(g3);
            c = fv * c + iv * gv;
            const float h = ov * tanhf_fast(c);

            const unsigned off = (((p ^ 1) * HBUF) + el * HPITCH + u0 + eu) * 4u;
            #pragma unroll
            for (int j = 0; j < CLS; ++j)
                asm volatile("st.shared::cluster.f32 [%0], %1;"
                             :: "r"(hb_peer[j] + off), "f"(h) : "memory");
        }
        __syncthreads();   // own h-stores visible locally for phase E

        // phase E (tid<256): coalesced g_lstm writeback from local buffer p^1
        if (tid < 256) {
            const int el2 = tid >> 5, ul = tid & 31;
            const float hv = dsm[HB_OFF + (p ^ 1) * HBUF + el2 * HPITCH + u0 + ul];
            g_lstm[s * NB + bg0 + el2][dir * NH2 + u0 + ul] = hv;
        }

        // phase F: cluster barrier (release peer stores / acquire for next read)
        asm volatile("barrier.cluster.arrive.aligned;" ::: "memory");
        asm volatile("barrier.cluster.wait.aligned;" ::: "memory");
        p ^= 1;
    }
}

// ------------------- emission features: lstm_out @ W_out^T + b_out ---------
__global__ __launch_bounds__(256) void k_feats(const float* __restrict__ Wout,
                                               const float* __restrict__ bout) {
    __shared__ float sW[NT][2 * NH2];
    const int tid = threadIdx.x;
    for (int i = tid; i < NT * 2 * NH2; i += 256) sW[i / (2 * NH2)][i % (2 * NH2)] = Wout[i];
    __syncthreads();

    const int warp = tid >> 5, lane = tid & 31;
    const int n = blockIdx.x * 8 + warp;
    const float4* row = (const float4*)&g_lstm[n][0];

    float pAcc[NT];
    #pragma unroll
    for (int t = 0; t < NT; ++t) pAcc[t] = 0.0f;
    for (int q = lane; q < 128; q += 32) {
        const float4 v = row[q];
        #pragma unroll
        for (int t = 0; t < NT; ++t) {
            const float4 wv = ((const float4*)&sW[t][0])[q];
            pAcc[t] += v.x * wv.x + v.y * wv.y + v.z * wv.z + v.w * wv.w;
        }
    }
    #pragma unroll
    for (int off = 16; off; off >>= 1)
        #pragma unroll
        for (int t = 0; t < NT; ++t)
            pAcc[t] += __shfl_down_sync(0xffffffffu, pAcc[t], off);
    if (lane == 0) {
        #pragma unroll
        for (int t = 0; t < NT; ++t) g_feats[n][t] = pAcc[t] + bout[t];
    }
}

// ------------------- Viterbi decode (1 warp per batch element) -------------
__global__ void k_viterbi(const float* __restrict__ trans, float* __restrict__ out) {
    const int b = blockIdx.x;
    const int lane = threadIdx.x;
    __shared__ float st[NT * NT];
    __shared__ unsigned char bp[NS][NT];
    for (int i = lane; i < NT * NT; i += 32) st[i] = trans[i];
    __syncwarp();

    float fv = (lane == IDX_START) ? 0.0f : -10000.0f;
    for (int s = 0; s < NS; ++s) {
        float best = -3.4e38f;
        int barg = 0;
        const float cur = fv;
        #pragma unroll
        for (int p = 0; p < NT; ++p) {
            const float fp = __shfl_sync(0xffffffffu, cur, p);
            if (lane < NT) {
                const float v = fp + st[lane * NT + p];
                if (v > best) { best = v; barg = p; }
            }
        }
        float feat = 0.0f;
        if (lane < NT) feat = g_feats[b * NS + s][lane];
        fv = best + feat;
        if (lane < NT) bp[s][lane] = (unsigned char)barg;
        __syncwarp();
    }
    float m = (lane < NT) ? (fv + st[IDX_STOP * NT + lane]) : -3.4e38f;
    int mi = lane;
    #pragma unroll
    for (int off = 16; off; off >>= 1) {
        const float om = __shfl_down_sync(0xffffffffu, m, off);
        const int oi = __shfl_down_sync(0xffffffffu, mi, off);
        if (om > m || (om == m && oi < mi)) { m = om; mi = oi; }
    }
    if (lane == 0) {
        out[b] = m;
        int best = mi;
        for (int s = NS - 1; s >= 0; --s) {
            out[NB + b * NS + s] = (float)best;
            best = bp[s][best];
        }
    }
}

// ------------------- launcher ----------------------------------------------
extern "C" void kernel_launch(void* const* d_in, const int* in_sizes, int n_in,
                              void* d_out, int out_size) {
    const int*   sent  = (const int*)d_in[0];
    const float* emb   = (const float*)d_in[1];
    const float* wih_f = (const float*)d_in[2];
    const float* whh_f = (const float*)d_in[3];
    const float* bih_f = (const float*)d_in[4];
    const float* bhh_f = (const float*)d_in[5];
    const float* wih_b = (const float*)d_in[6];
    const float* whh_b = (const float*)d_in[7];
    const float* bih_b = (const float*)d_in[8];
    const float* bhh_b = (const float*)d_in[9];
    const float* Wout  = (const float*)d_in[10];
    const float* bout  = (const float*)d_in[11];

    const float *trans, *h0, *c0;
    if (n_in > 12 && in_sizes[12] == NT * NT) {
        trans = (const float*)d_in[12];
        h0    = (const float*)d_in[13];
        c0    = (const float*)d_in[14];
    } else {
        h0    = (const float*)d_in[12];
        c0    = (const float*)d_in[13];
        trans = (const float*)d_in[14];
    }

    static int smem_set = 0;
    const int lstm_smem = DSM_FLOATS * (int)sizeof(float);  // ~185.5 KB
    if (!smem_set) {
        cudaFuncSetAttribute(k_lstm, cudaFuncAttributeMaxDynamicSharedMemorySize,
                             lstm_smem);
        smem_set = 1;
    }

    {
        dim3 gg(NM / 128, NG / 128);
        k_input_gemm<<<gg, 256>>>(sent, emb, wih_f, bih_f, bhh_f, 0);
        k_input_gemm<<<gg, 256>>>(sent, emb, wih_b, bih_b, bhh_b, 1);
    }
    k_lstm<<<128, 512, lstm_smem>>>(whh_f, whh_b, h0, c0);
    k_feats<<<NM / 8, 256>>>(Wout, bout);
    k_viterbi<<<NB, 32>>>(trans, (float*)d_out);
}